// round 16
// baseline (speedup 1.0000x reference)
#include <cuda_runtime.h>
#include <cuda_bf16.h>
#include <math.h>

#define Nn    20000
#define Ee    320000
#define HEADS 8
#define EDIM  8
#define NEG   0.2f

typedef unsigned long long ull;

// ---------------- scratch ----------------
__device__ float g_M1[EDIM * HEADS];
__device__ float g_M2[EDIM];
__device__ __align__(16) int   g_deg[Nn];
__device__ int   g_rowoff[Nn + 1];
__device__ int   g_cursor[Nn];
__device__ int   g_csr_src[Ee];
__device__ __align__(16) float g_csr_ae1[(size_t)Ee * HEADS];   // slot-major [pos][8]
__device__ float g_csr_ae2[Ee];
__device__ __align__(16) float g_h1[(size_t)Nn * 256];
__device__ __align__(16) float g_hmid[(size_t)Nn * 256];
__device__ __align__(16) float g_h2[(size_t)Nn * 32];
__device__ float g_asrc1[(size_t)Nn * HEADS];
__device__ float g_adst1[(size_t)Nn * HEADS];
__device__ float g_asrc2[Nn];
__device__ float g_adst2[Nn];

// ---------------- helpers ----------------
__device__ __forceinline__ float lrelu(float x) { return x > 0.f ? x : NEG * x; }
__device__ __forceinline__ float wredSum(float v) {
    #pragma unroll
    for (int o = 16; o > 0; o >>= 1) v += __shfl_xor_sync(0xffffffffu, v, o);
    return v;
}
__device__ __forceinline__ void fma2(ull& d, ull a, ull b) {
    asm("fma.rn.f32x2 %0, %1, %2, %3;" : "=l"(d) : "l"(a), "l"(b), "l"(d));
}
__device__ __forceinline__ ull pk2(float lo, float hi) {
    ull r; asm("mov.b64 %0, {%1,%2};" : "=l"(r) : "f"(lo), "f"(hi)); return r;
}
__device__ __forceinline__ float2 upk(ull v) {
    float2 r; asm("mov.b64 {%0,%1}, %2;" : "=f"(r.x), "=f"(r.y) : "l"(v)); return r;
}

// ---------------- K_pre: fold attention vectors into edge projections ------
__global__ void k_pre(const float* __restrict__ We1, const float* __restrict__ ae1,
                      const float* __restrict__ We2, const float* __restrict__ ae2) {
    int t = threadIdx.x;
    if (t < 64) {
        int d = t / 8, h = t % 8;
        float s = 0.f;
        #pragma unroll
        for (int c = 0; c < 32; c++) s += We1[d * 256 + h * 32 + c] * ae1[h * 32 + c];
        g_M1[d * 8 + h] = s;
    }
    if (t < 8) {
        float s = 0.f;
        #pragma unroll
        for (int c = 0; c < 32; c++) s += We2[t * 32 + c] * ae2[c];
        g_M2[t] = s;
    }
}

// ---------------- K_deg: count in-degree ----------------
__global__ void k_deg(const int* __restrict__ ei) {
    int e = blockIdx.x * blockDim.x + threadIdx.x;
    if (e < Ee) atomicAdd(&g_deg[ei[Ee + e]], 1);
}

// ---------------- K_scan: vectorized warp-shuffle exclusive scan -----------
__global__ void k_scan() {
    __shared__ int wsum[32];
    int t = threadIdx.x;               // 1024 threads; 1000 active, 20 nodes each
    int s = t * 20;
    int d[20];
    int loc = 0;
    if (t < 1000) {
        const int4* p = (const int4*)&g_deg[s];
        #pragma unroll
        for (int q = 0; q < 5; q++) {
            int4 u = p[q];
            d[q * 4 + 0] = u.x; d[q * 4 + 1] = u.y;
            d[q * 4 + 2] = u.z; d[q * 4 + 3] = u.w;
            loc += u.x + u.y + u.z + u.w;
        }
    }
    int lane = t & 31, wid = t >> 5;
    int v = loc;
    #pragma unroll
    for (int o = 1; o < 32; o <<= 1) {
        int u = __shfl_up_sync(0xffffffffu, v, o);
        if (lane >= o) v += u;
    }
    if (lane == 31) wsum[wid] = v;
    __syncthreads();
    if (wid == 0) {
        int w = wsum[lane];
        #pragma unroll
        for (int o = 1; o < 32; o <<= 1) {
            int u = __shfl_up_sync(0xffffffffu, w, o);
            if (lane >= o) w += u;
        }
        wsum[lane] = w;
    }
    __syncthreads();
    int excl = v - loc + (wid ? wsum[wid - 1] : 0);
    if (t < 1000) {
        int run = excl;
        #pragma unroll
        for (int i = 0; i < 20; i++) {
            g_rowoff[s + i] = run;
            g_cursor[s + i] = run;
            run += d[i];
        }
    }
    if (t == 1023) g_rowoff[Nn] = wsum[31];
}

// ---------------- K_fill: embed + edge attention + CSR scatter -------------
__global__ void k_fill(const int* __restrict__ ei, const float* __restrict__ ea,
                       const float* __restrict__ Wse, const float* __restrict__ bse) {
    int e = blockIdx.x * blockDim.x + threadIdx.x;
    if (e >= Ee) return;
    int sN = ei[e], dN = ei[Ee + e];
    float a0 = ea[2 * e], a1 = ea[2 * e + 1];
    float vv[8];
    #pragma unroll
    for (int j = 0; j < 8; j++)
        vv[j] = fmaxf(a0 * __ldg(&Wse[j]) + a1 * __ldg(&Wse[8 + j]) + __ldg(&bse[j]), 0.f);
    float ae1v[8];
    #pragma unroll
    for (int h = 0; h < 8; h++) {
        float s = 0.f;
        #pragma unroll
        for (int dd = 0; dd < 8; dd++) s += vv[dd] * g_M1[dd * 8 + h];
        ae1v[h] = s;
    }
    float ae2v = 0.f;
    #pragma unroll
    for (int dd = 0; dd < 8; dd++) ae2v += vv[dd] * g_M2[dd];

    int pos = atomicAdd(&g_cursor[dN], 1);
    g_csr_src[pos] = sN;
    *(float4*)&g_csr_ae1[(size_t)pos * 8]     = make_float4(ae1v[0], ae1v[1], ae1v[2], ae1v[3]);
    *(float4*)&g_csr_ae1[(size_t)pos * 8 + 4] = make_float4(ae1v[4], ae1v[5], ae1v[6], ae1v[7]);
    g_csr_ae2[pos] = ae2v;
}

// ---------------- K_gemm1: h1 = x @ W1, 128x64 tiles, f32x2 FMA ------------
#define GM 128
#define GN 64
#define GK 16
__global__ void k_gemm1(const float* __restrict__ X, const float* __restrict__ W) {
    __shared__ float As2[GK][2 * GM];   // A duplicated into pairs: [k][2m],[k][2m+1]
    __shared__ float Bs[GK][GN];
    int tid = threadIdx.x;              // 256
    int tx = tid % 16, ty = tid / 16;
    int brow = blockIdx.x * GM, bcol = blockIdx.y * GN;

    ull acc[8][2];
    #pragma unroll
    for (int i = 0; i < 8; i++) { acc[i][0] = 0ull; acc[i][1] = 0ull; }

    for (int k0 = 0; k0 < 256; k0 += GK) {
        #pragma unroll
        for (int l = 0; l < 2; l++) {
            int idx = tid * 2 + l;              // 0..511, 4 float4 per row
            int r = idx >> 2, kc = (idx & 3) * 4;
            int gr = brow + r;
            float4 v = (gr < Nn) ? *(const float4*)&X[(size_t)gr * 256 + k0 + kc]
                                 : make_float4(0.f, 0.f, 0.f, 0.f);
            *(ull*)&As2[kc + 0][2 * r] = pk2(v.x, v.x);
            *(ull*)&As2[kc + 1][2 * r] = pk2(v.y, v.y);
            *(ull*)&As2[kc + 2][2 * r] = pk2(v.z, v.z);
            *(ull*)&As2[kc + 3][2 * r] = pk2(v.w, v.w);
        }
        {
            int r = tid >> 4, c = (tid & 15) * 4;    // 16 rows x 16 f4
            *(float4*)&Bs[r][c] = *(const float4*)&W[(size_t)(k0 + r) * 256 + bcol + c];
        }
        __syncthreads();
        #pragma unroll
        for (int kk = 0; kk < GK; kk++) {
            ulonglong2 b2 = *(const ulonglong2*)&Bs[kk][tx * 4];
            #pragma unroll
            for (int i = 0; i < 8; i++) {
                ull a2 = *(const ull*)&As2[kk][2 * (ty * 8 + i)];
                fma2(acc[i][0], a2, b2.x);
                fma2(acc[i][1], a2, b2.y);
            }
        }
        __syncthreads();
    }
    #pragma unroll
    for (int i = 0; i < 8; i++) {
        int gr = brow + ty * 8 + i;
        if (gr < Nn) {
            float2 p0 = upk(acc[i][0]), p1 = upk(acc[i][1]);
            *(float4*)&g_h1[(size_t)gr * 256 + bcol + tx * 4] =
                make_float4(p0.x, p0.y, p1.x, p1.y);
        }
    }
}

// ---------------- K_attn1: per-node attention scalars for conv1 ------------
__global__ void k_attn1(const float* __restrict__ as1, const float* __restrict__ ad1) {
    int warp = threadIdx.x / 32, lane = threadIdx.x % 32;
    int n = blockIdx.x * 8 + warp;
    #pragma unroll
    for (int h = 0; h < 8; h++) {
        float val = g_h1[(size_t)n * 256 + h * 32 + lane];
        float s = wredSum(val * __ldg(&as1[h * 32 + lane]));
        float d = wredSum(val * __ldg(&ad1[h * 32 + lane]));
        if (lane == 0) { g_asrc1[(size_t)n * 8 + h] = s; g_adst1[(size_t)n * 8 + h] = d; }
    }
}

// ---------------- K_conv1: single-pass softmax-aggregate (warp per head) ---
__global__ void k_conv1(const float* __restrict__ b1) {
    int n = blockIdx.x;
    int h = threadIdx.x / 32, lane = threadIdx.x % 32;
    int beg = g_rowoff[n], end = g_rowoff[n + 1];
    float adst = g_adst1[(size_t)n * 8 + h];

    float aesum = 0.f, denom = 0.f, acc = 0.f;
    for (int base = beg; base < end; base += 32) {
        int jj = base + lane;
        float al = 0.f; int s = 0;
        if (jj < end) {
            s = g_csr_src[jj];
            float aej = g_csr_ae1[(size_t)jj * 8 + h];
            aesum += aej;
            al = __expf(lrelu(g_asrc1[(size_t)s * 8 + h] + adst + aej));
            denom += al;
        }
        int cnt = min(32, end - base);
        if (cnt == 32) {
            #pragma unroll
            for (int i = 0; i < 32; i++) {
                float a = __shfl_sync(0xffffffffu, al, i);
                int ss  = __shfl_sync(0xffffffffu, s, i);
                acc += a * __ldg(&g_h1[(size_t)ss * 256 + h * 32 + lane]);
            }
        } else {
            for (int i = 0; i < cnt; i++) {
                float a = __shfl_sync(0xffffffffu, al, i);
                int ss  = __shfl_sync(0xffffffffu, s, i);
                acc += a * __ldg(&g_h1[(size_t)ss * 256 + h * 32 + lane]);
            }
        }
    }
    aesum = wredSum(aesum);
    denom = wredSum(denom);

    int deg = end - beg;
    float aloop = aesum / fmaxf((float)deg, 1.f);   // mean(aedge) == e_mean @ M1
    float selfE = __expf(lrelu(g_asrc1[(size_t)n * 8 + h] + adst + aloop));
    denom += selfE;
    acc += selfE * g_h1[(size_t)n * 256 + h * 32 + lane];

    float v = acc / denom + __ldg(&b1[h * 32 + lane]);
    g_hmid[(size_t)n * 256 + h * 32 + lane] = fmaxf(v, 0.f);
}

// ---------------- K_gemm2: h2 = hmid @ W2 (+ fused attn scalars) -----------
__global__ void k_gemm2(const float* __restrict__ W2, const float* __restrict__ as2,
                        const float* __restrict__ ad2) {
    __shared__ float Wt[32 * 260];     // transposed, padded: Wt[c*260+k]
    __shared__ float Xs[8 * 256];
    int tid = threadIdx.x;             // 256
    for (int i = tid; i < 256 * 32; i += 256) {
        int k = i >> 5, c = i & 31;
        Wt[c * 260 + k] = W2[i];
    }
    int row0 = blockIdx.x * 8;
    for (int i = tid; i < 2048 / 4; i += 256)
        *(float4*)&Xs[i * 4] = *(const float4*)&g_hmid[(size_t)row0 * 256 + i * 4];
    __syncthreads();

    int r = tid >> 5, c = tid & 31;
    ull acc0 = 0ull, acc1 = 0ull;
    #pragma unroll 8
    for (int kk = 0; kk < 64; kk++) {
        ulonglong2 xv = *(const ulonglong2*)&Xs[r * 256 + kk * 4];
        ulonglong2 wv = *(const ulonglong2*)&Wt[c * 260 + kk * 4];
        fma2(acc0, xv.x, wv.x);
        fma2(acc1, xv.y, wv.y);
    }
    float2 p0 = upk(acc0), p1 = upk(acc1);
    float acc = (p0.x + p0.y) + (p1.x + p1.y);

    int n = row0 + r;
    g_h2[(size_t)n * 32 + c] = acc;
    float s1 = wredSum(acc * __ldg(&as2[c]));
    float s2 = wredSum(acc * __ldg(&ad2[c]));
    if (c == 0) { g_asrc2[n] = s1; g_adst2[n] = s2; }
}

// ---------------- K_conv2: single-pass (warp per node) ---------------------
__global__ void k_conv2(const float* __restrict__ b2, float* __restrict__ out) {
    int warp = threadIdx.x / 32, lane = threadIdx.x % 32;
    int n = blockIdx.x * 8 + warp;
    int beg = g_rowoff[n], end = g_rowoff[n + 1];
    float adst = g_adst2[n];

    float aesum = 0.f, denom = 0.f, acc = 0.f;
    for (int base = beg; base < end; base += 32) {
        int jj = base + lane;
        float al = 0.f; int s = 0;
        if (jj < end) {
            s = g_csr_src[jj];
            float aej = g_csr_ae2[jj];
            aesum += aej;
            al = __expf(lrelu(g_asrc2[s] + adst + aej));
            denom += al;
        }
        int cnt = min(32, end - base);
        if (cnt == 32) {
            #pragma unroll
            for (int i = 0; i < 32; i++) {
                float a = __shfl_sync(0xffffffffu, al, i);
                int ss  = __shfl_sync(0xffffffffu, s, i);
                acc += a * __ldg(&g_h2[(size_t)ss * 32 + lane]);
            }
        } else {
            for (int i = 0; i < cnt; i++) {
                float a = __shfl_sync(0xffffffffu, al, i);
                int ss  = __shfl_sync(0xffffffffu, s, i);
                acc += a * __ldg(&g_h2[(size_t)ss * 32 + lane]);
            }
        }
    }
    aesum = wredSum(aesum);
    denom = wredSum(denom);

    int deg = end - beg;
    float aloop = aesum / fmaxf((float)deg, 1.f);
    float selfE = __expf(lrelu(g_asrc2[n] + adst + aloop));
    denom += selfE;
    acc += selfE * g_h2[(size_t)n * 32 + lane];

    out[(size_t)n * 32 + lane] = acc / denom + __ldg(&b2[lane]);
}

// ---------------- launcher ----------------
extern "C" void kernel_launch(void* const* d_in, const int* in_sizes, int n_in,
                              void* d_out, int out_size) {
    const float* x   = (const float*)d_in[0];
    const int*   ei  = (const int*)  d_in[1];
    const float* ea  = (const float*)d_in[2];
    const float* Wse = (const float*)d_in[3];
    const float* bse = (const float*)d_in[4];
    const float* W1  = (const float*)d_in[5];
    const float* as1 = (const float*)d_in[6];
    const float* ad1 = (const float*)d_in[7];
    const float* We1 = (const float*)d_in[8];
    const float* ae1 = (const float*)d_in[9];
    const float* b1  = (const float*)d_in[10];
    const float* W2  = (const float*)d_in[11];
    const float* as2 = (const float*)d_in[12];
    const float* ad2 = (const float*)d_in[13];
    const float* We2 = (const float*)d_in[14];
    const float* ae2 = (const float*)d_in[15];
    const float* b2  = (const float*)d_in[16];
    float* out = (float*)d_out;

    void* degPtr = nullptr;
    cudaGetSymbolAddress(&degPtr, g_deg);
    cudaMemsetAsync(degPtr, 0, Nn * sizeof(int), 0);

    k_pre<<<1, 64>>>(We1, ae1, We2, ae2);
    k_deg<<<(Ee + 255) / 256, 256>>>(ei);
    k_scan<<<1, 1024>>>();
    k_fill<<<(Ee + 255) / 256, 256>>>(ei, ea, Wse, bse);
    dim3 g1((Nn + GM - 1) / GM, 256 / GN);
    k_gemm1<<<g1, 256>>>(x, W1);
    k_attn1<<<Nn / 8, 256>>>(as1, ad1);
    k_conv1<<<Nn, 256>>>(b1);
    k_gemm2<<<Nn / 8, 256>>>(W2, as2, ad2);
    k_conv2<<<Nn / 8, 256>>>(b2, out);
}

// round 17
// speedup vs baseline: 1.0027x; 1.0027x over previous
#include <cuda_runtime.h>
#include <cuda_bf16.h>
#include <math.h>

#define Nn    20000
#define Ee    320000
#define HEADS 8
#define EDIM  8
#define NEG   0.2f

typedef unsigned long long ull;

// ---------------- scratch ----------------
__device__ float g_M1[EDIM * HEADS];
__device__ float g_M2[EDIM];
__device__ __align__(16) int   g_deg[Nn];
__device__ int   g_rowoff[Nn + 1];
__device__ int   g_cursor[Nn];
__device__ int   g_csr_src[Ee];
__device__ __align__(16) float g_csr_ae1[(size_t)Ee * HEADS];   // slot-major [pos][8]
__device__ float g_csr_ae2[Ee];
__device__ __align__(16) float g_h1[(size_t)Nn * 256];
__device__ __align__(16) float g_hmid[(size_t)Nn * 256];
__device__ __align__(16) float g_h2[(size_t)Nn * 32];
__device__ float g_asrc1[(size_t)Nn * HEADS];
__device__ float g_adst1[(size_t)Nn * HEADS];
__device__ float g_asrc2[Nn];
__device__ float g_adst2[Nn];

// ---------------- helpers ----------------
__device__ __forceinline__ float lrelu(float x) { return x > 0.f ? x : NEG * x; }
__device__ __forceinline__ float wredSum(float v) {
    #pragma unroll
    for (int o = 16; o > 0; o >>= 1) v += __shfl_xor_sync(0xffffffffu, v, o);
    return v;
}
__device__ __forceinline__ void fma2(ull& d, ull a, ull b) {
    asm("fma.rn.f32x2 %0, %1, %2, %3;" : "=l"(d) : "l"(a), "l"(b), "l"(d));
}
__device__ __forceinline__ ull pk2(float lo, float hi) {
    ull r; asm("mov.b64 %0, {%1,%2};" : "=l"(r) : "f"(lo), "f"(hi)); return r;
}
__device__ __forceinline__ float2 upk(ull v) {
    float2 r; asm("mov.b64 {%0,%1}, %2;" : "=f"(r.x), "=f"(r.y) : "l"(v)); return r;
}

// ---------------- K_pre: fold attention vectors into edge projections ------
__global__ void k_pre(const float* __restrict__ We1, const float* __restrict__ ae1,
                      const float* __restrict__ We2, const float* __restrict__ ae2) {
    int t = threadIdx.x;
    if (t < 64) {
        int d = t / 8, h = t % 8;
        float s = 0.f;
        #pragma unroll
        for (int c = 0; c < 32; c++) s += We1[d * 256 + h * 32 + c] * ae1[h * 32 + c];
        g_M1[d * 8 + h] = s;
    }
    if (t < 8) {
        float s = 0.f;
        #pragma unroll
        for (int c = 0; c < 32; c++) s += We2[t * 32 + c] * ae2[c];
        g_M2[t] = s;
    }
}

// ---------------- K_deg: count in-degree ----------------
__global__ void k_deg(const int* __restrict__ ei) {
    int e = blockIdx.x * blockDim.x + threadIdx.x;
    if (e < Ee) atomicAdd(&g_deg[ei[Ee + e]], 1);
}

// ---------------- K_scan: vectorized warp-shuffle exclusive scan -----------
__global__ void k_scan() {
    __shared__ int wsum[32];
    int t = threadIdx.x;               // 1024 threads; 1000 active, 20 nodes each
    int s = t * 20;
    int d[20];
    int loc = 0;
    if (t < 1000) {
        const int4* p = (const int4*)&g_deg[s];
        #pragma unroll
        for (int q = 0; q < 5; q++) {
            int4 u = p[q];
            d[q * 4 + 0] = u.x; d[q * 4 + 1] = u.y;
            d[q * 4 + 2] = u.z; d[q * 4 + 3] = u.w;
            loc += u.x + u.y + u.z + u.w;
        }
    }
    int lane = t & 31, wid = t >> 5;
    int v = loc;
    #pragma unroll
    for (int o = 1; o < 32; o <<= 1) {
        int u = __shfl_up_sync(0xffffffffu, v, o);
        if (lane >= o) v += u;
    }
    if (lane == 31) wsum[wid] = v;
    __syncthreads();
    if (wid == 0) {
        int w = wsum[lane];
        #pragma unroll
        for (int o = 1; o < 32; o <<= 1) {
            int u = __shfl_up_sync(0xffffffffu, w, o);
            if (lane >= o) w += u;
        }
        wsum[lane] = w;
    }
    __syncthreads();
    int excl = v - loc + (wid ? wsum[wid - 1] : 0);
    if (t < 1000) {
        int run = excl;
        #pragma unroll
        for (int i = 0; i < 20; i++) {
            g_rowoff[s + i] = run;
            g_cursor[s + i] = run;
            run += d[i];
        }
    }
    if (t == 1023) g_rowoff[Nn] = wsum[31];
}

// ---------------- K_fill: embed + edge attention + CSR scatter -------------
__global__ void k_fill(const int* __restrict__ ei, const float* __restrict__ ea,
                       const float* __restrict__ Wse, const float* __restrict__ bse) {
    int e = blockIdx.x * blockDim.x + threadIdx.x;
    if (e >= Ee) return;
    int sN = ei[e], dN = ei[Ee + e];
    float a0 = ea[2 * e], a1 = ea[2 * e + 1];
    float vv[8];
    #pragma unroll
    for (int j = 0; j < 8; j++)
        vv[j] = fmaxf(a0 * __ldg(&Wse[j]) + a1 * __ldg(&Wse[8 + j]) + __ldg(&bse[j]), 0.f);
    float ae1v[8];
    #pragma unroll
    for (int h = 0; h < 8; h++) {
        float s = 0.f;
        #pragma unroll
        for (int dd = 0; dd < 8; dd++) s += vv[dd] * g_M1[dd * 8 + h];
        ae1v[h] = s;
    }
    float ae2v = 0.f;
    #pragma unroll
    for (int dd = 0; dd < 8; dd++) ae2v += vv[dd] * g_M2[dd];

    int pos = atomicAdd(&g_cursor[dN], 1);
    g_csr_src[pos] = sN;
    *(float4*)&g_csr_ae1[(size_t)pos * 8]     = make_float4(ae1v[0], ae1v[1], ae1v[2], ae1v[3]);
    *(float4*)&g_csr_ae1[(size_t)pos * 8 + 4] = make_float4(ae1v[4], ae1v[5], ae1v[6], ae1v[7]);
    g_csr_ae2[pos] = ae2v;
}

// ---------------- K_gemm1: h1 = x @ W1, 128x64 tiles, f32x2 FMA ------------
#define GM 128
#define GN 64
#define GK 16
__global__ void k_gemm1(const float* __restrict__ X, const float* __restrict__ W) {
    __shared__ float As2[GK][2 * GM];   // A duplicated into pairs: [k][2m],[k][2m+1]
    __shared__ float Bs[GK][GN];
    int tid = threadIdx.x;              // 256
    int tx = tid % 16, ty = tid / 16;
    int brow = blockIdx.x * GM, bcol = blockIdx.y * GN;

    ull acc[8][2];
    #pragma unroll
    for (int i = 0; i < 8; i++) { acc[i][0] = 0ull; acc[i][1] = 0ull; }

    for (int k0 = 0; k0 < 256; k0 += GK) {
        #pragma unroll
        for (int l = 0; l < 2; l++) {
            int idx = tid * 2 + l;              // 0..511, 4 float4 per row
            int r = idx >> 2, kc = (idx & 3) * 4;
            int gr = brow + r;
            float4 v = (gr < Nn) ? *(const float4*)&X[(size_t)gr * 256 + k0 + kc]
                                 : make_float4(0.f, 0.f, 0.f, 0.f);
            *(ull*)&As2[kc + 0][2 * r] = pk2(v.x, v.x);
            *(ull*)&As2[kc + 1][2 * r] = pk2(v.y, v.y);
            *(ull*)&As2[kc + 2][2 * r] = pk2(v.z, v.z);
            *(ull*)&As2[kc + 3][2 * r] = pk2(v.w, v.w);
        }
        {
            int r = tid >> 4, c = (tid & 15) * 4;    // 16 rows x 16 f4
            *(float4*)&Bs[r][c] = *(const float4*)&W[(size_t)(k0 + r) * 256 + bcol + c];
        }
        __syncthreads();
        #pragma unroll
        for (int kk = 0; kk < GK; kk++) {
            ulonglong2 b2 = *(const ulonglong2*)&Bs[kk][tx * 4];
            #pragma unroll
            for (int i = 0; i < 8; i++) {
                ull a2 = *(const ull*)&As2[kk][2 * (ty * 8 + i)];
                fma2(acc[i][0], a2, b2.x);
                fma2(acc[i][1], a2, b2.y);
            }
        }
        __syncthreads();
    }
    #pragma unroll
    for (int i = 0; i < 8; i++) {
        int gr = brow + ty * 8 + i;
        if (gr < Nn) {
            float2 p0 = upk(acc[i][0]), p1 = upk(acc[i][1]);
            *(float4*)&g_h1[(size_t)gr * 256 + bcol + tx * 4] =
                make_float4(p0.x, p0.y, p1.x, p1.y);
        }
    }
}

// ---------------- K_attn1: per-node attention scalars for conv1 ------------
__global__ void k_attn1(const float* __restrict__ as1, const float* __restrict__ ad1) {
    int warp = threadIdx.x / 32, lane = threadIdx.x % 32;
    int n = blockIdx.x * 8 + warp;
    #pragma unroll
    for (int h = 0; h < 8; h++) {
        float val = g_h1[(size_t)n * 256 + h * 32 + lane];
        float s = wredSum(val * __ldg(&as1[h * 32 + lane]));
        float d = wredSum(val * __ldg(&ad1[h * 32 + lane]));
        if (lane == 0) { g_asrc1[(size_t)n * 8 + h] = s; g_adst1[(size_t)n * 8 + h] = d; }
    }
}

// ---------------- K_conv1: single-pass softmax-aggregate (warp per head) ---
__global__ void k_conv1(const float* __restrict__ b1) {
    int n = blockIdx.x;
    int h = threadIdx.x / 32, lane = threadIdx.x % 32;
    int beg = g_rowoff[n], end = g_rowoff[n + 1];
    float adst = g_adst1[(size_t)n * 8 + h];

    float aesum = 0.f, denom = 0.f, acc = 0.f;
    for (int base = beg; base < end; base += 32) {
        int jj = base + lane;
        float al = 0.f; int s = 0;
        if (jj < end) {
            s = g_csr_src[jj];
            float aej = g_csr_ae1[(size_t)jj * 8 + h];
            aesum += aej;
            al = __expf(lrelu(g_asrc1[(size_t)s * 8 + h] + adst + aej));
            denom += al;
        }
        int cnt = min(32, end - base);
        if (cnt == 32) {
            #pragma unroll
            for (int i = 0; i < 32; i++) {
                float a = __shfl_sync(0xffffffffu, al, i);
                int ss  = __shfl_sync(0xffffffffu, s, i);
                acc += a * __ldg(&g_h1[(size_t)ss * 256 + h * 32 + lane]);
            }
        } else {
            for (int i = 0; i < cnt; i++) {
                float a = __shfl_sync(0xffffffffu, al, i);
                int ss  = __shfl_sync(0xffffffffu, s, i);
                acc += a * __ldg(&g_h1[(size_t)ss * 256 + h * 32 + lane]);
            }
        }
    }
    aesum = wredSum(aesum);
    denom = wredSum(denom);

    int deg = end - beg;
    float aloop = aesum / fmaxf((float)deg, 1.f);   // mean(aedge) == e_mean @ M1
    float selfE = __expf(lrelu(g_asrc1[(size_t)n * 8 + h] + adst + aloop));
    denom += selfE;
    acc += selfE * g_h1[(size_t)n * 256 + h * 32 + lane];

    float v = acc / denom + __ldg(&b1[h * 32 + lane]);
    g_hmid[(size_t)n * 256 + h * 32 + lane] = fmaxf(v, 0.f);
}

// ---------------- K_gemm2: h2 = hmid @ W2 (+ fused attn scalars) -----------
__global__ void k_gemm2(const float* __restrict__ W2, const float* __restrict__ as2,
                        const float* __restrict__ ad2) {
    __shared__ float Wt[32 * 260];     // transposed, padded: Wt[c*260+k]
    __shared__ float Xs[8 * 256];
    int tid = threadIdx.x;             // 256
    for (int i = tid; i < 256 * 32; i += 256) {
        int k = i >> 5, c = i & 31;
        Wt[c * 260 + k] = W2[i];
    }
    int row0 = blockIdx.x * 8;
    for (int i = tid; i < 2048 / 4; i += 256)
        *(float4*)&Xs[i * 4] = *(const float4*)&g_hmid[(size_t)row0 * 256 + i * 4];
    __syncthreads();

    int r = tid >> 5, c = tid & 31;
    ull acc0 = 0ull, acc1 = 0ull;
    #pragma unroll 8
    for (int kk = 0; kk < 64; kk++) {
        ulonglong2 xv = *(const ulonglong2*)&Xs[r * 256 + kk * 4];
        ulonglong2 wv = *(const ulonglong2*)&Wt[c * 260 + kk * 4];
        fma2(acc0, xv.x, wv.x);
        fma2(acc1, xv.y, wv.y);
    }
    float2 p0 = upk(acc0), p1 = upk(acc1);
    float acc = (p0.x + p0.y) + (p1.x + p1.y);

    int n = row0 + r;
    g_h2[(size_t)n * 32 + c] = acc;
    float s1 = wredSum(acc * __ldg(&as2[c]));
    float s2 = wredSum(acc * __ldg(&ad2[c]));
    if (c == 0) { g_asrc2[n] = s1; g_adst2[n] = s2; }
}

// ---------------- K_conv2: single-pass (warp per node) ---------------------
__global__ void k_conv2(const float* __restrict__ b2, float* __restrict__ out) {
    int warp = threadIdx.x / 32, lane = threadIdx.x % 32;
    int n = blockIdx.x * 8 + warp;
    int beg = g_rowoff[n], end = g_rowoff[n + 1];
    float adst = g_adst2[n];

    float aesum = 0.f, denom = 0.f, acc = 0.f;
    for (int base = beg; base < end; base += 32) {
        int jj = base + lane;
        float al = 0.f; int s = 0;
        if (jj < end) {
            s = g_csr_src[jj];
            float aej = g_csr_ae2[jj];
            aesum += aej;
            al = __expf(lrelu(g_asrc2[s] + adst + aej));
            denom += al;
        }
        int cnt = min(32, end - base);
        if (cnt == 32) {
            #pragma unroll
            for (int i = 0; i < 32; i++) {
                float a = __shfl_sync(0xffffffffu, al, i);
                int ss  = __shfl_sync(0xffffffffu, s, i);
                acc += a * __ldg(&g_h2[(size_t)ss * 32 + lane]);
            }
        } else {
            for (int i = 0; i < cnt; i++) {
                float a = __shfl_sync(0xffffffffu, al, i);
                int ss  = __shfl_sync(0xffffffffu, s, i);
                acc += a * __ldg(&g_h2[(size_t)ss * 32 + lane]);
            }
        }
    }
    aesum = wredSum(aesum);
    denom = wredSum(denom);

    int deg = end - beg;
    float aloop = aesum / fmaxf((float)deg, 1.f);
    float selfE = __expf(lrelu(g_asrc2[n] + adst + aloop));
    denom += selfE;
    acc += selfE * g_h2[(size_t)n * 32 + lane];

    out[(size_t)n * 32 + lane] = acc / denom + __ldg(&b2[lane]);
}

// ---------------- launcher ----------------
extern "C" void kernel_launch(void* const* d_in, const int* in_sizes, int n_in,
                              void* d_out, int out_size) {
    const float* x   = (const float*)d_in[0];
    const int*   ei  = (const int*)  d_in[1];
    const float* ea  = (const float*)d_in[2];
    const float* Wse = (const float*)d_in[3];
    const float* bse = (const float*)d_in[4];
    const float* W1  = (const float*)d_in[5];
    const float* as1 = (const float*)d_in[6];
    const float* ad1 = (const float*)d_in[7];
    const float* We1 = (const float*)d_in[8];
    const float* ae1 = (const float*)d_in[9];
    const float* b1  = (const float*)d_in[10];
    const float* W2  = (const float*)d_in[11];
    const float* as2 = (const float*)d_in[12];
    const float* ad2 = (const float*)d_in[13];
    const float* We2 = (const float*)d_in[14];
    const float* ae2 = (const float*)d_in[15];
    const float* b2  = (const float*)d_in[16];
    float* out = (float*)d_out;

    void* degPtr = nullptr;
    cudaGetSymbolAddress(&degPtr, g_deg);
    cudaMemsetAsync(degPtr, 0, Nn * sizeof(int), 0);

    k_pre<<<1, 64>>>(We1, ae1, We2, ae2);
    k_deg<<<(Ee + 255) / 256, 256>>>(ei);
    k_scan<<<1, 1024>>>();
    k_fill<<<(Ee + 255) / 256, 256>>>(ei, ea, Wse, bse);
    dim3 g1((Nn + GM - 1) / GM, 256 / GN);
    k_gemm1<<<g1, 256>>>(x, W1);
    k_attn1<<<Nn / 8, 256>>>(as1, ad1);
    k_conv1<<<Nn, 256>>>(b1);
    k_gemm2<<<Nn / 8, 256>>>(W2, as2, ad2);
    k_conv2<<<Nn / 8, 256>>>(b2, out);
}